// round 5
// baseline (speedup 1.0000x reference)
#include <cuda_runtime.h>

// B=2048 rows, N=8192 cols.
// Per row: r = |y_true - y_pred|; Newton in beta=1/eps on
// h(beta)=log(sum sinh(beta*r)) - ln(2N) (same unique root as the reference's
// 20 eps-space Newton iterations, converged well past the 1e-3 tolerance;
// early exit at |step| < 1e-5*beta). Then eps=1/beta (floored), betaF =
// 1/(eps+1e-6) as in the reference; q = sinh(betaF*r);
// qmax = sinh(betaF*rmax) analytically (sinh monotone on r>=0);
// Lambda' = 0.99*Lambda + 0.1*(0.9*q/(qmax+1e-20) + 0.1);
// loss = mean((Lambda'*r)^2) via per-row partials + tiny second kernel.
// Output: d_out[0] = loss, d_out[1..B*N] = Lambda' (row-major).
//
// Perf notes (round-5): latency-bound before, not MUFU-bound.
//  - __launch_bounds__(1024,2): 32-reg cap -> 2 CTAs/SM, 7 waves, bubbles filled.
//  - 1 barrier per Newton iteration: double-buffered partials; every warp
//    redundantly reduces and every thread redundantly does the scalar Newton
//    update (uniform), removing the serialized t==0 section + second barrier.

#define BDIM 1024
#define VPT 8

static constexpr int B = 2048;
static constexpr int N = 8192;
static constexpr float LOG_2N = 9.70406052783923f;  // ln(2*N) = ln(16384)

__device__ float g_row_loss[B];

__device__ __forceinline__ float warp_sum(float v) {
#pragma unroll
    for (int o = 16; o; o >>= 1) v += __shfl_xor_sync(0xffffffffu, v, o);
    return v;
}
__device__ __forceinline__ float warp_max(float v) {
#pragma unroll
    for (int o = 16; o; o >>= 1) v = fmaxf(v, __shfl_xor_sync(0xffffffffu, v, o));
    return v;
}

__global__ __launch_bounds__(BDIM, 2)
void custom_loss_row_kernel(const float* __restrict__ y_pred,
                            const float* __restrict__ y_true,
                            const float* __restrict__ Lam,
                            float* __restrict__ out_lambda) {
    const int b = blockIdx.x;
    const size_t base = (size_t)b * N;
    const int t = threadIdx.x;
    const int lane = t & 31;
    const int wid = t >> 5;

    __shared__ float smax[32];
    __shared__ float sS[2][32];
    __shared__ float sT[2][32];

    // ---- residuals: float4 loads, 8 elems/thread ----
    const float4* yp4 = (const float4*)(y_pred + base);
    const float4* yt4 = (const float4*)(y_true + base);
    float r[VPT];
    {
        const float4 p0 = yp4[t], g0 = yt4[t];
        r[0] = fabsf(g0.x - p0.x); r[1] = fabsf(g0.y - p0.y);
        r[2] = fabsf(g0.z - p0.z); r[3] = fabsf(g0.w - p0.w);
        const float4 p1 = yp4[t + BDIM], g1 = yt4[t + BDIM];
        r[4] = fabsf(g1.x - p1.x); r[5] = fabsf(g1.y - p1.y);
        r[6] = fabsf(g1.z - p1.z); r[7] = fabsf(g1.w - p1.w);
    }

    // ---- row max(r): 1 barrier, redundant cross-warp reduce ----
    float m = r[0];
#pragma unroll
    for (int i = 1; i < VPT; i++) m = fmaxf(m, r[i]);
    m = warp_max(m);
    if (lane == 0) smax[wid] = m;
    __syncthreads();
    const float rmax = warp_max(smax[lane]);  // every warp, uniform result

    // beta0 = 1/eps0, eps0 = max(rmax,1e-8)/(ln(2N)+1e-8)  (reference init)
    float beta = (LOG_2N + 1e-8f) / fmaxf(rmax, 1e-8f);

    // ---- Newton on h(beta)=log(S)-ln(2N), S=sum(e^x - e^-x) ----
    // 1 barrier/iter: write partials to parity buffer, sync, all warps
    // redundantly reduce + all threads redundantly compute the update.
#pragma unroll 1
    for (int itn = 0; itn < 12; itn++) {
        float S = 0.0f;  // sum (e^x - e^-x) = 2*sum sinh
        float T = 0.0f;  // sum r*(e^x + e^-x) = 2*sum r*cosh
#pragma unroll
        for (int i = 0; i < VPT; i++) {
            const float x  = beta * r[i];
            const float E  = __expf(x);
            const float Em = __expf(-x);
            S += (E - Em);
            T = fmaf(E + Em, r[i], T);
        }
        S = warp_sum(S);
        T = warp_sum(T);
        const int pb = itn & 1;
        if (lane == 0) { sS[pb][wid] = S; sT[pb][wid] = T; }
        __syncthreads();
        const float S2 = warp_sum(sS[pb][lane]);
        const float T2 = warp_sum(sT[pb][lane]);
        // h = log(S2) - ln(2N);  h' = T2/S2;  Newton step db = h*S2/T2
        const float h  = __logf(S2) - LOG_2N;
        const float db = h * __fdividef(S2, T2);
        float nb = beta - db;
        nb = fminf(fmaxf(nb, 0.05f * beta), 4.0f * beta);  // safety clamp
        const bool done = fabsf(db) < 1e-5f * beta;        // uniform
        beta = nb;
        if (done) break;
    }

    // ---- final beta exactly as reference: eps floor, then +1e-6 ----
    const float eps = fmaxf(__fdividef(1.0f, beta), 1e-8f);
    const float betaF = __fdividef(1.0f, eps + 1e-6f);

    // qmax analytically: sinh monotone on r>=0 -> max at rmax
    const float xm = betaF * rmax;
    const float qmax = 0.5f * (__expf(xm) - __expf(-xm));
    const float inv_qm = __fdividef(1.0f, qmax + 1e-20f);

    // ---- q, Lambda update, per-row loss partial ----
    // (float4 Lambda loads; scalar stores: out base is +1 float, misaligned)
    const float4* L4 = (const float4*)(Lam + base);
    float lsum = 0.0f;
    {
        const float4 l0 = L4[t];
        const float la0[4] = {l0.x, l0.y, l0.z, l0.w};
#pragma unroll
        for (int i = 0; i < 4; i++) {
            const float x  = betaF * r[i];
            const float q  = 0.5f * (__expf(x) - __expf(-x));
            const float qn = q * inv_qm;
            const float lam = fmaf(0.99f, la0[i], 0.1f * fmaf(0.9f, qn, 0.1f));
            out_lambda[base + 4 * t + i] = lam;
            const float z = lam * r[i];
            lsum = fmaf(z, z, lsum);
        }
        const float4 l1 = L4[t + BDIM];
        const float la1[4] = {l1.x, l1.y, l1.z, l1.w};
#pragma unroll
        for (int i = 0; i < 4; i++) {
            const float x  = betaF * r[4 + i];
            const float q  = 0.5f * (__expf(x) - __expf(-x));
            const float qn = q * inv_qm;
            const float lam = fmaf(0.99f, la1[i], 0.1f * fmaf(0.9f, qn, 0.1f));
            out_lambda[base + 4 * (t + BDIM) + i] = lam;
            const float z = lam * r[4 + i];
            lsum = fmaf(z, z, lsum);
        }
    }
    lsum = warp_sum(lsum);
    __syncthreads();  // all loop-buffer reads done before reuse of sS[0]
    if (lane == 0) sS[0][wid] = lsum;
    __syncthreads();
    if (t == 0) {
        float v = 0.0f;
#pragma unroll
        for (int i = 0; i < 32; i++) v += sS[0][i];
        g_row_loss[b] = v;
    }
}

__global__ void loss_reduce_kernel(float* __restrict__ out_loss) {
    const int t = threadIdx.x;  // 1024 threads
    float s = g_row_loss[t] + g_row_loss[t + 1024];
    s = warp_sum(s);
    __shared__ float sm[32];
    if ((t & 31) == 0) sm[t >> 5] = s;
    __syncthreads();
    if (t < 32) {
        float v = warp_sum(sm[t]);
        if (t == 0) out_loss[0] = v * (1.0f / 16777216.0f);  // / (B*N)
    }
}

extern "C" void kernel_launch(void* const* d_in, const int* in_sizes, int n_in,
                              void* d_out, int out_size) {
    const float* y_pred = (const float*)d_in[0];
    const float* y_true = (const float*)d_in[1];
    const float* Lam    = (const float*)d_in[2];
    // d_in[3] = it (unused by the cosh branch)

    float* out = (float*)d_out;       // out[0] = loss
    float* out_lambda = out + 1;      // out[1..] = updated Lambda

    custom_loss_row_kernel<<<B, BDIM>>>(y_pred, y_true, Lam, out_lambda);
    loss_reduce_kernel<<<1, BDIM>>>(out);
}

// round 7
// speedup vs baseline: 1.0134x; 1.0134x over previous
#include <cuda_runtime.h>

// B=2048 rows, N=8192 cols. One CTA per row, 512 threads x 16 elems.
// Per row: r = |y_true - y_pred|; Newton in beta=1/eps on
// h(beta)=log(sum sinh(beta*r)) - ln(2N) (same unique root as the reference's
// 20 eps-space Newton iterations, converged far past the 1e-3 tolerance):
// 2 warm-start iterations on log(sum e^{beta r}) - ln(2N) (1 exp/elem,
// monotone from the reference init since e^{beta0*rmax} = 2N), then full
// iterations (2 exp/elem) with early exit. eps=1/beta (floored), betaF =
// 1/(eps+1e-6) per reference; q = sinh(betaF*r);
// qmax = sinh(betaF*rmax) analytically (sinh monotone on r>=0);
// Lambda' = 0.99*Lambda + 0.1*(0.9*q/(qmax+1e-20) + 0.1);
// loss = mean((Lambda'*r)^2) via per-row partials + tiny second kernel.
// Output: d_out[0] = loss, d_out[1..B*N] = Lambda' (row-major).
//
// Round-7 fix: round 6 deadlocked because the cross-warp reduce ran with only
// 16 threads of warp 0 active under full-mask shuffles. Partial arrays are now
// padded to 32 slots (slots 16..31 = 0, neutral for max since r>=0 and for
// sums; never rewritten since wid<16) and the reduce runs on the FULL warp 0.

#define BDIM 512
#define VPT 16
#define NWARP (BDIM / 32)   // 16

static constexpr int B = 2048;
static constexpr int N = 8192;
static constexpr float LOG_2N = 9.70406052783923f;  // ln(2*N) = ln(16384)

__device__ float g_row_loss[B];

__device__ __forceinline__ float warp_sum(float v) {
#pragma unroll
    for (int o = 16; o; o >>= 1) v += __shfl_xor_sync(0xffffffffu, v, o);
    return v;
}
__device__ __forceinline__ float warp_max(float v) {
#pragma unroll
    for (int o = 16; o; o >>= 1) v = fmaxf(v, __shfl_xor_sync(0xffffffffu, v, o));
    return v;
}

__global__ __launch_bounds__(BDIM, 2)
void custom_loss_row_kernel(const float* __restrict__ y_pred,
                            const float* __restrict__ y_true,
                            const float* __restrict__ Lam,
                            float* __restrict__ out_lambda) {
    const int b = blockIdx.x;
    const size_t base = (size_t)b * N;
    const int t = threadIdx.x;
    const int lane = t & 31;
    const int wid = t >> 5;

    __shared__ float s1s[32];   // 16 warp partials + 16 zero-pad
    __shared__ float s2s[32];
    __shared__ float bcast;
    __shared__ int   sdone;

    // zero-pad slots 16..31 once (neutral for max since r>=0, and for sums;
    // wid<16 so these are never rewritten). Covered by the rowmax barrier.
    if (t >= NWARP && t < 32) { s1s[t] = 0.0f; s2s[t] = 0.0f; }

    // ---- residuals: float4 loads, 16 elems/thread ----
    const float4* yp4 = (const float4*)(y_pred + base);
    const float4* yt4 = (const float4*)(y_true + base);
    float r[VPT];
#pragma unroll
    for (int c = 0; c < 4; c++) {
        const float4 p = yp4[t + c * BDIM];
        const float4 g = yt4[t + c * BDIM];
        r[4 * c + 0] = fabsf(g.x - p.x);
        r[4 * c + 1] = fabsf(g.y - p.y);
        r[4 * c + 2] = fabsf(g.z - p.z);
        r[4 * c + 3] = fabsf(g.w - p.w);
    }

    // ---- row max(r) ----
    float m = r[0];
#pragma unroll
    for (int i = 1; i < VPT; i++) m = fmaxf(m, r[i]);
    m = warp_max(m);
    if (lane == 0) s1s[wid] = m;
    __syncthreads();
    if (t < 32) {
        float v = warp_max(s1s[lane]);   // full warp, full-mask shuffles
        if (t == 0) bcast = v;
    }
    __syncthreads();
    const float rmax = bcast;

    // beta0 = 1/eps0, eps0 = max(rmax,1e-8)/(ln(2N)+1e-8)  (reference init)
    float beta = (LOG_2N + 1e-8f) / fmaxf(rmax, 1e-8f);

    // ---- phase 1: 2 warm-start iterations (e^{+x} only, 1 MUFU/elem) ----
    // Solves sum(e^{beta*r}) = 2N. At beta0, e^{beta0*rmax} = 2N so h>=0 and
    // beta decreases monotonically; lands ~1% below the true root.
#pragma unroll 1
    for (int itn = 0; itn < 2; itn++) {
        float S = 0.0f, T = 0.0f;
#pragma unroll
        for (int i = 0; i < VPT; i++) {
            const float E = __expf(beta * r[i]);
            S += E;
            T = fmaf(E, r[i], T);
        }
        S = warp_sum(S);
        T = warp_sum(T);
        if (lane == 0) { s1s[wid] = S; s2s[wid] = T; }
        __syncthreads();
        if (t < 32) {
            const float S2 = warp_sum(s1s[lane]);
            const float T2 = warp_sum(s2s[lane]);
            if (t == 0) {
                const float h  = __logf(S2) - LOG_2N;
                const float db = h * __fdividef(S2, T2);
                float nb = beta - db;
                bcast = fminf(fmaxf(nb, 0.05f * beta), 4.0f * beta);
            }
        }
        __syncthreads();
        beta = bcast;
    }

    // ---- phase 2: full Newton on h(beta)=log(S)-ln(2N), S=sum(e^x-e^-x) ----
#pragma unroll 1
    for (int itn = 0; itn < 10; itn++) {
        float S = 0.0f, T = 0.0f;
#pragma unroll
        for (int i = 0; i < VPT; i++) {
            const float x  = beta * r[i];
            const float E  = __expf(x);
            const float Em = __expf(-x);
            S += (E - Em);
            T = fmaf(E + Em, r[i], T);
        }
        S = warp_sum(S);
        T = warp_sum(T);
        if (lane == 0) { s1s[wid] = S; s2s[wid] = T; }
        __syncthreads();
        if (t < 32) {
            const float S2 = warp_sum(s1s[lane]);
            const float T2 = warp_sum(s2s[lane]);
            if (t == 0) {
                const float h  = __logf(S2) - LOG_2N;
                const float db = h * __fdividef(S2, T2);
                float nb = beta - db;
                bcast = fminf(fmaxf(nb, 0.05f * beta), 4.0f * beta);
                sdone = (fabsf(db) < 1e-5f * beta) ? 1 : 0;
            }
        }
        __syncthreads();
        beta = bcast;
        if (sdone) break;  // uniform across block
    }

    // ---- final beta exactly as reference: eps floor, then +1e-6 ----
    const float eps = fmaxf(__fdividef(1.0f, beta), 1e-8f);
    const float betaF = __fdividef(1.0f, eps + 1e-6f);

    // qmax analytically: sinh monotone on r>=0 -> max at rmax
    const float xm = betaF * rmax;
    const float qmax = 0.5f * (__expf(xm) - __expf(-xm));
    const float inv_qm = __fdividef(1.0f, qmax + 1e-20f);

    // ---- q, Lambda update, per-row loss partial ----
    // (float4 Lambda loads; scalar stores: out base is +1 float, misaligned)
    const float4* L4 = (const float4*)(Lam + base);
    float lsum = 0.0f;
#pragma unroll
    for (int c = 0; c < 4; c++) {
        const float4 l = L4[t + c * BDIM];
        const float la[4] = {l.x, l.y, l.z, l.w};
#pragma unroll
        for (int i = 0; i < 4; i++) {
            const float rv = r[4 * c + i];
            const float x  = betaF * rv;
            const float q  = 0.5f * (__expf(x) - __expf(-x));
            const float qn = q * inv_qm;
            const float lam = fmaf(0.99f, la[i], 0.1f * fmaf(0.9f, qn, 0.1f));
            out_lambda[base + 4 * (t + c * BDIM) + i] = lam;
            const float z = lam * rv;
            lsum = fmaf(z, z, lsum);
        }
    }
    lsum = warp_sum(lsum);
    __syncthreads();  // loop-buffer reads done before s1s reuse
    if (lane == 0) s1s[wid] = lsum;
    __syncthreads();
    if (t == 0) {
        float v = 0.0f;
#pragma unroll
        for (int i = 0; i < NWARP; i++) v += s1s[i];
        g_row_loss[b] = v;
    }
}

__global__ void loss_reduce_kernel(float* __restrict__ out_loss) {
    const int t = threadIdx.x;  // 1024 threads
    float s = g_row_loss[t] + g_row_loss[t + 1024];
    s = warp_sum(s);
    __shared__ float sm[32];
    if ((t & 31) == 0) sm[t >> 5] = s;
    __syncthreads();
    if (t < 32) {
        float v = warp_sum(sm[t]);
        if (t == 0) out_loss[0] = v * (1.0f / 16777216.0f);  // / (B*N)
    }
}

extern "C" void kernel_launch(void* const* d_in, const int* in_sizes, int n_in,
                              void* d_out, int out_size) {
    const float* y_pred = (const float*)d_in[0];
    const float* y_true = (const float*)d_in[1];
    const float* Lam    = (const float*)d_in[2];
    // d_in[3] = it (unused by the cosh branch)

    float* out = (float*)d_out;       // out[0] = loss
    float* out_lambda = out + 1;      // out[1..] = updated Lambda

    custom_loss_row_kernel<<<B, BDIM>>>(y_pred, y_true, Lam, out_lambda);
    loss_reduce_kernel<<<1, 1024>>>(out);
}